// round 6
// baseline (speedup 1.0000x reference)
#include <cuda_runtime.h>
#include <cuda_bf16.h>
#include <math.h>
#include <stdint.h>

#define DTC 0.001
#define Pdim 1024
#define Hdim 256
#define Ldim 16384
#define NKC  16        // K chunks of 64 (K = 1024 per GEMM)
#define STAGE_BYTES 49152   // Ahi 16K | Alo 16K | Bhi 8K | Blo 8K

// ---------------------------------------------------------------------------
// Device-global scratch (allocation-free rule)
// ---------------------------------------------------------------------------
__device__ __align__(16) float2  g_ab[Pdim];     // fp32 A_bar
__device__ __align__(16) float2  g_cf[Pdim];     // (A_bar-1)/Ac
__device__ __align__(16) double2 g_lg[Pdim];     // log(A_bar) fp64
// A planes [variant: r_hi, r_lo, i_hi, i_lo, s_hi, s_lo][kc(16)][m=h(256)][kk(64)]
__device__ __align__(128) __nv_bfloat16 g_A[6][(size_t)16 * 256 * 64];
// B planes same variant order, [kc(16)][n=l(16384)][kk(64)]  (32 MB each)
__device__ __align__(128) __nv_bfloat16 g_B[6][(size_t)16 * 16384 * 64];
// Partial GEMM outputs Gr, Gi, Gm  (16 MB each)
__device__ __align__(128) float g_G[3][(size_t)256 * 16384];

// ---------------------------------------------------------------------------
// helpers
// ---------------------------------------------------------------------------
__device__ __forceinline__ uint32_t s2u(const void* p) {
    uint32_t a;
    asm("{ .reg .u64 t; cvta.to.shared.u64 t, %1; cvt.u32.u64 %0, t; }"
        : "=r"(a) : "l"(p));
    return a;
}

__device__ __forceinline__ void cpa(uint32_t dst, const void* src) {
    asm volatile("cp.async.cg.shared.global [%0], [%1], 16;"
                 :: "r"(dst), "l"(src) : "memory");
}

__device__ __forceinline__ void ldm4(uint32_t* r, uint32_t a) {
    asm volatile("ldmatrix.sync.aligned.m8n8.x4.shared.b16 {%0,%1,%2,%3}, [%4];"
                 : "=r"(r[0]), "=r"(r[1]), "=r"(r[2]), "=r"(r[3]) : "r"(a));
}

__device__ __forceinline__ void mma16816(float* d, const uint32_t* a,
                                         uint32_t b0, uint32_t b1) {
    asm volatile(
        "mma.sync.aligned.m16n8k16.row.col.f32.bf16.bf16.f32 "
        "{%0,%1,%2,%3}, {%4,%5,%6,%7}, {%8,%9}, {%0,%1,%2,%3};"
        : "+f"(d[0]), "+f"(d[1]), "+f"(d[2]), "+f"(d[3])
        : "r"(a[0]), "r"(a[1]), "r"(a[2]), "r"(a[3]), "r"(b0), "r"(b1));
}

// ---------------------------------------------------------------------------
// k_pre: per-p constants (fp64 transcendentals once per p)
// ---------------------------------------------------------------------------
__global__ void k_pre(const float* __restrict__ A) {
    int p = blockIdx.x * blockDim.x + threadIdx.x;
    if (p >= Pdim) return;
    float ar = A[2 * p], ai = A[2 * p + 1];
    double e = exp((double)ar * DTC), th = (double)ai * DTC;
    float abr = (float)(e * cos(th));
    float abi = (float)(e * sin(th));
    float nr = abr - 1.0f, ni = abi;
    float den = ar * ar + ai * ai;
    g_ab[p] = make_float2(abr, abi);
    g_cf[p] = make_float2((nr * ar + ni * ai) / den, (ni * ar - nr * ai) / den);
    g_lg[p] = make_double2(0.5 * log((double)abr * abr + (double)abi * abi),
                           atan2((double)abi, (double)abr));
}

// ---------------------------------------------------------------------------
// k_setupA: W[h,p] = C[h,p]*coef[p]*B[p,h]; 3 variants (Wr, Wi, Wr+Wi) with
// bf16 hi/lo split. Layout [kc][m=h][kk=64], element (h, p).
// ---------------------------------------------------------------------------
__global__ void k_setupA(const float* __restrict__ B, const float* __restrict__ C) {
    int idx = blockIdx.x * 256 + threadIdx.x;     // over P*H
    int p = idx & (Pdim - 1), h = idx >> 10;
    float2 cf = g_cf[p];
    float br = B[(p * Hdim + h) * 2], bi = B[(p * Hdim + h) * 2 + 1];
    float bbr = cf.x * br - cf.y * bi;
    float bbi = cf.x * bi + cf.y * br;
    float cr = C[(h * Pdim + p) * 2], ci = C[(h * Pdim + p) * 2 + 1];
    float wr = cr * bbr - ci * bbi;
    float wi = cr * bbi + ci * bbr;
    float ws = wr + wi;

    size_t o = ((size_t)(p >> 6) * 256 + h) * 64 + (p & 63);
    __nv_bfloat16 hr = __float2bfloat16_rn(wr);
    __nv_bfloat16 hi = __float2bfloat16_rn(wi);
    __nv_bfloat16 hs = __float2bfloat16_rn(ws);
    g_A[0][o] = hr; g_A[1][o] = __float2bfloat16_rn(wr - __bfloat162float(hr));
    g_A[2][o] = hi; g_A[3][o] = __float2bfloat16_rn(wi - __bfloat162float(hi));
    g_A[4][o] = hs; g_A[5][o] = __float2bfloat16_rn(ws - __bfloat162float(hs));
}

// ---------------------------------------------------------------------------
// k_genB: V[p,l] via fp32 recurrence (seeded fp64 every 128 l); writes 3
// variants (Vr, Vi, Vr+Vi) hi/lo.
// ---------------------------------------------------------------------------
__global__ void k_genB() {
    int wid = blockIdx.x * 8 + (threadIdx.x >> 5);   // 4096 warps
    int lane = threadIdx.x & 31;
    int pg = wid & 31, seg = wid >> 5;               // seg 0..127
    int p = pg * 32 + lane;

    float2 ab = g_ab[p];
    double2 lg = g_lg[p];
    int l0 = seg * 128;
    double m = exp(lg.x * (double)l0), a = lg.y * (double)l0;
    float vr = (float)(m * cos(a));
    float vi = (float)(m * sin(a));

    const size_t kcbase = (size_t)(p >> 6) * 16384;
    const int kk = p & 63;

    #pragma unroll 4
    for (int t = 0; t < 128; t++) {
        int l = l0 + t;
        float vs = vr + vi;
        __nv_bfloat16 hr = __float2bfloat16_rn(vr);
        __nv_bfloat16 hi = __float2bfloat16_rn(vi);
        __nv_bfloat16 hs = __float2bfloat16_rn(vs);
        size_t o = (kcbase + l) * 64 + kk;
        g_B[0][o] = hr; g_B[1][o] = __float2bfloat16_rn(vr - __bfloat162float(hr));
        g_B[2][o] = hi; g_B[3][o] = __float2bfloat16_rn(vi - __bfloat162float(hi));
        g_B[4][o] = hs; g_B[5][o] = __float2bfloat16_rn(vs - __bfloat162float(hs));
        float nvr = vr * ab.x - vi * ab.y;
        float nvi = vr * ab.y + vi * ab.x;
        vr = nvr; vi = nvi;
    }
}

// ---------------------------------------------------------------------------
// k_gemm: z-batched 3 real GEMMs, CTA tile 128m x 64n, 256 thr (8 warps 4x2,
// warp tile 32x32), 2 CTAs/SM, 2-stage cp.async pipeline (96 KB smem).
// Stage layout: [Ahi 16K][Alo 16K][Bhi 8K][Blo 8K].
// ---------------------------------------------------------------------------
__global__ __launch_bounds__(256, 2) void k_gemm() {
    extern __shared__ char smp[];
    const int tid  = threadIdx.x;
    const int lane = tid & 31;
    const int wid  = tid >> 5;
    const int wm   = wid >> 1;            // 0..3
    const int wn   = wid & 1;             // 0..1
    const int m0   = blockIdx.x * 128;
    const int n0   = blockIdx.y * 64;
    const int z    = blockIdx.z;          // 0=r, 1=i, 2=s
    const uint32_t sb = s2u(smp);

    const __nv_bfloat16* Agh = g_A[2 * z];
    const __nv_bfloat16* Agl = g_A[2 * z + 1];
    const __nv_bfloat16* Bgh = g_B[2 * z];
    const __nv_bfloat16* Bgl = g_B[2 * z + 1];

    float acc[2][4][4];
    #pragma unroll
    for (int i = 0; i < 2; i++)
        #pragma unroll
        for (int j = 0; j < 4; j++)
            #pragma unroll
            for (int t = 0; t < 4; t++) acc[i][j][t] = 0.0f;

    // staging: A planes 128 rows x 8 cols (1024 slots, 4/thread),
    //          B planes  64 rows x 8 cols (512 slots, 2/thread)
    const int arow = tid >> 1, acol2 = (tid & 1) << 2;  // A: 2 thr/row, 4 cols each
    const int brow = tid >> 2, bcol2 = (tid & 3) << 1;  // B: 4 thr/row, 2 cols each

    auto issue = [&](int kc, int s) {
        uint32_t st = sb + s * STAGE_BYTES;
        #pragma unroll
        for (int j = 0; j < 4; j++) {
            int col = acol2 + j;
            uint32_t d = st + arow * 128 + ((col ^ (arow & 7)) << 4);
            size_t oA = ((size_t)kc * 256 + m0 + arow) * 64 + col * 8;
            cpa(d,         Agh + oA);
            cpa(d + 16384, Agl + oA);
        }
        #pragma unroll
        for (int j = 0; j < 2; j++) {
            int col = bcol2 + j;
            uint32_t d = st + 32768 + brow * 128 + ((col ^ (brow & 7)) << 4);
            size_t oB = ((size_t)kc * 16384 + n0 + brow) * 64 + col * 8;
            cpa(d,        Bgh + oB);
            cpa(d + 8192, Bgl + oB);
        }
        asm volatile("cp.async.commit_group;" ::: "memory");
    };

    const int r15 = lane & 15, h16 = lane >> 4;
    const int rA0 = wm * 32 + r15, rA1 = rA0 + 16;
    const int rB0 = wn * 32 + r15, rB1 = rB0 + 16;

    issue(0, 0);

    for (int k = 0; k < NKC; k++) {
        const int s = k & 1;
        if (k + 1 < NKC) {
            issue(k + 1, s ^ 1);
            asm volatile("cp.async.wait_group 1;" ::: "memory");
        } else {
            asm volatile("cp.async.wait_group 0;" ::: "memory");
        }
        __syncthreads();

        const uint32_t sA = sb + s * STAGE_BYTES;
        const uint32_t sB = sA + 32768;

        #pragma unroll
        for (int ks = 0; ks < 4; ks++) {
            const int cc = 2 * ks + h16;
            uint32_t a0[4], a1[4], al0[4], al1[4];
            uint32_t bh0[4], bh1[4], bl0[4], bl1[4];
            uint32_t oA0 = rA0 * 128 + ((cc ^ (rA0 & 7)) << 4);
            uint32_t oA1 = rA1 * 128 + ((cc ^ (rA1 & 7)) << 4);
            uint32_t oB0 = rB0 * 128 + ((cc ^ (rB0 & 7)) << 4);
            uint32_t oB1 = rB1 * 128 + ((cc ^ (rB1 & 7)) << 4);

            ldm4(a0,  sA + oA0);
            ldm4(a1,  sA + oA1);
            ldm4(al0, sA + 16384 + oA0);
            ldm4(al1, sA + 16384 + oA1);
            ldm4(bh0, sB + oB0);
            ldm4(bh1, sB + oB1);
            ldm4(bl0, sB + 8192 + oB0);
            ldm4(bl1, sB + 8192 + oB1);

            // hi*hi
            mma16816(acc[0][0], a0, bh0[0], bh0[2]);
            mma16816(acc[0][1], a0, bh0[1], bh0[3]);
            mma16816(acc[0][2], a0, bh1[0], bh1[2]);
            mma16816(acc[0][3], a0, bh1[1], bh1[3]);
            mma16816(acc[1][0], a1, bh0[0], bh0[2]);
            mma16816(acc[1][1], a1, bh0[1], bh0[3]);
            mma16816(acc[1][2], a1, bh1[0], bh1[2]);
            mma16816(acc[1][3], a1, bh1[1], bh1[3]);
            // hi*lo
            mma16816(acc[0][0], a0, bl0[0], bl0[2]);
            mma16816(acc[0][1], a0, bl0[1], bl0[3]);
            mma16816(acc[0][2], a0, bl1[0], bl1[2]);
            mma16816(acc[0][3], a0, bl1[1], bl1[3]);
            mma16816(acc[1][0], a1, bl0[0], bl0[2]);
            mma16816(acc[1][1], a1, bl0[1], bl0[3]);
            mma16816(acc[1][2], a1, bl1[0], bl1[2]);
            mma16816(acc[1][3], a1, bl1[1], bl1[3]);
            // lo*hi
            mma16816(acc[0][0], al0, bh0[0], bh0[2]);
            mma16816(acc[0][1], al0, bh0[1], bh0[3]);
            mma16816(acc[0][2], al0, bh1[0], bh1[2]);
            mma16816(acc[0][3], al0, bh1[1], bh1[3]);
            mma16816(acc[1][0], al1, bh0[0], bh0[2]);
            mma16816(acc[1][1], al1, bh0[1], bh0[3]);
            mma16816(acc[1][2], al1, bh1[0], bh1[2]);
            mma16816(acc[1][3], al1, bh1[1], bh1[3]);
        }
        __syncthreads();
    }

    // Epilogue -> fp32 partial plane
    float* G = g_G[z];
    const int mrow = lane >> 2, ncol = (lane & 3) * 2;
    #pragma unroll
    for (int im = 0; im < 2; im++) {
        int m = m0 + wm * 32 + im * 16 + mrow;
        #pragma unroll
        for (int jn = 0; jn < 4; jn++) {
            int n = n0 + wn * 32 + jn * 8 + ncol;
            float* p = G + (size_t)m * Ldim + n;
            *(float2*)p = make_float2(acc[im][jn][0], acc[im][jn][1]);
            *(float2*)(p + (size_t)8 * Ldim) = make_float2(acc[im][jn][2], acc[im][jn][3]);
        }
    }
}

// ---------------------------------------------------------------------------
// k_comb: out[h][l] = (Gr-Gi, Gm-Gr-Gi), vectorized float4.
// ---------------------------------------------------------------------------
__global__ void k_comb(float4* __restrict__ out) {
    size_t idx = (size_t)blockIdx.x * 256 + threadIdx.x;   // over H*L/4
    const float4* Gr = (const float4*)g_G[0];
    const float4* Gi = (const float4*)g_G[1];
    const float4* Gm = (const float4*)g_G[2];
    float4 r = Gr[idx], i = Gi[idx], m = Gm[idx];
    out[2 * idx] = make_float4(r.x - i.x, m.x - r.x - i.x,
                               r.y - i.y, m.y - r.y - i.y);
    out[2 * idx + 1] = make_float4(r.z - i.z, m.z - r.z - i.z,
                                   r.w - i.w, m.w - r.w - i.w);
}

// ---------------------------------------------------------------------------
extern "C" void kernel_launch(void* const* d_in, const int* in_sizes, int n_in,
                              void* d_out, int out_size) {
    const float* A = (const float*)d_in[0];
    const float* B = (const float*)d_in[1];
    const float* C = (const float*)d_in[2];

    cudaFuncSetAttribute(k_gemm, cudaFuncAttributeMaxDynamicSharedMemorySize, 98304);

    k_pre<<<4, 256>>>(A);
    k_setupA<<<1024, 256>>>(B, C);
    k_genB<<<512, 256>>>();
    k_gemm<<<dim3(2, 256, 3), 256, 98304>>>();
    k_comb<<<4096, 256>>>((float4*)d_out);
}

// round 7
// speedup vs baseline: 1.0111x; 1.0111x over previous
#include <cuda_runtime.h>
#include <cuda_bf16.h>
#include <math.h>
#include <stdint.h>

#define DTC 0.001
#define Pdim 1024
#define Hdim 256
#define Ldim 16384
#define NKC  16             // K chunks of 64 (K = 1024 per GEMM)
#define STAGE_BYTES 98304   // Ahi 16K | Alo 16K | Bhi 32K | Blo 32K

// ---------------------------------------------------------------------------
// Device-global scratch (allocation-free rule)
// ---------------------------------------------------------------------------
__device__ __align__(16) float2  g_ab[Pdim];     // fp32 A_bar
__device__ __align__(16) float2  g_cf[Pdim];     // (A_bar-1)/Ac
__device__ __align__(16) double2 g_lg[Pdim];     // log(A_bar) fp64
// A planes [variant: r_hi, r_lo, i_hi, i_lo, s_hi, s_lo][kc(16)][m=h(256)][kk(64)]
__device__ __align__(128) __nv_bfloat16 g_A[6][(size_t)16 * 256 * 64];
// B planes same variant order, [kc(16)][n=l(16384)][kk(64)]  (32 MB each)
__device__ __align__(128) __nv_bfloat16 g_B[6][(size_t)16 * 16384 * 64];
// Partial GEMM outputs Gr, Gi, Gm  (16 MB each)
__device__ __align__(128) float g_G[3][(size_t)256 * 16384];

// ---------------------------------------------------------------------------
// helpers
// ---------------------------------------------------------------------------
__device__ __forceinline__ uint32_t s2u(const void* p) {
    uint32_t a;
    asm("{ .reg .u64 t; cvta.to.shared.u64 t, %1; cvt.u32.u64 %0, t; }"
        : "=r"(a) : "l"(p));
    return a;
}

__device__ __forceinline__ void cpa(uint32_t dst, const void* src) {
    asm volatile("cp.async.cg.shared.global [%0], [%1], 16;"
                 :: "r"(dst), "l"(src) : "memory");
}

__device__ __forceinline__ void ldm4(uint32_t* r, uint32_t a) {
    asm volatile("ldmatrix.sync.aligned.m8n8.x4.shared.b16 {%0,%1,%2,%3}, [%4];"
                 : "=r"(r[0]), "=r"(r[1]), "=r"(r[2]), "=r"(r[3]) : "r"(a));
}

__device__ __forceinline__ void mma16816(float* d, const uint32_t* a,
                                         uint32_t b0, uint32_t b1) {
    asm volatile(
        "mma.sync.aligned.m16n8k16.row.col.f32.bf16.bf16.f32 "
        "{%0,%1,%2,%3}, {%4,%5,%6,%7}, {%8,%9}, {%0,%1,%2,%3};"
        : "+f"(d[0]), "+f"(d[1]), "+f"(d[2]), "+f"(d[3])
        : "r"(a[0]), "r"(a[1]), "r"(a[2]), "r"(a[3]), "r"(b0), "r"(b1));
}

// ---------------------------------------------------------------------------
// k_pre: per-p constants (fp64 transcendentals once per p)
// ---------------------------------------------------------------------------
__global__ void k_pre(const float* __restrict__ A) {
    int p = blockIdx.x * blockDim.x + threadIdx.x;
    if (p >= Pdim) return;
    float ar = A[2 * p], ai = A[2 * p + 1];
    double e = exp((double)ar * DTC), th = (double)ai * DTC;
    float abr = (float)(e * cos(th));
    float abi = (float)(e * sin(th));
    float nr = abr - 1.0f, ni = abi;
    float den = ar * ar + ai * ai;
    g_ab[p] = make_float2(abr, abi);
    g_cf[p] = make_float2((nr * ar + ni * ai) / den, (ni * ar - nr * ai) / den);
    g_lg[p] = make_double2(0.5 * log((double)abr * abr + (double)abi * abi),
                           atan2((double)abi, (double)abr));
}

// ---------------------------------------------------------------------------
// k_setupA: W[h,p] = C[h,p]*coef[p]*B[p,h]; 3 variants (Wr, Wi, Wr+Wi) with
// bf16 hi/lo split. Layout [kc][m=h][kk=64], element (h, p).
// ---------------------------------------------------------------------------
__global__ void k_setupA(const float* __restrict__ B, const float* __restrict__ C) {
    int idx = blockIdx.x * 256 + threadIdx.x;     // over P*H
    int p = idx & (Pdim - 1), h = idx >> 10;
    float2 cf = g_cf[p];
    float br = B[(p * Hdim + h) * 2], bi = B[(p * Hdim + h) * 2 + 1];
    float bbr = cf.x * br - cf.y * bi;
    float bbi = cf.x * bi + cf.y * br;
    float cr = C[(h * Pdim + p) * 2], ci = C[(h * Pdim + p) * 2 + 1];
    float wr = cr * bbr - ci * bbi;
    float wi = cr * bbi + ci * bbr;
    float ws = wr + wi;

    size_t o = ((size_t)(p >> 6) * 256 + h) * 64 + (p & 63);
    __nv_bfloat16 hr = __float2bfloat16_rn(wr);
    __nv_bfloat16 hi = __float2bfloat16_rn(wi);
    __nv_bfloat16 hs = __float2bfloat16_rn(ws);
    g_A[0][o] = hr; g_A[1][o] = __float2bfloat16_rn(wr - __bfloat162float(hr));
    g_A[2][o] = hi; g_A[3][o] = __float2bfloat16_rn(wi - __bfloat162float(hi));
    g_A[4][o] = hs; g_A[5][o] = __float2bfloat16_rn(ws - __bfloat162float(hs));
}

// ---------------------------------------------------------------------------
// k_genB: V[p,l] via fp32 recurrence (seeded fp64 every 128 l); writes 3
// variants (Vr, Vi, Vr+Vi) hi/lo.
// ---------------------------------------------------------------------------
__global__ void k_genB() {
    int wid = blockIdx.x * 8 + (threadIdx.x >> 5);   // 4096 warps
    int lane = threadIdx.x & 31;
    int pg = wid & 31, seg = wid >> 5;               // seg 0..127
    int p = pg * 32 + lane;

    float2 ab = g_ab[p];
    double2 lg = g_lg[p];
    int l0 = seg * 128;
    double m = exp(lg.x * (double)l0), a = lg.y * (double)l0;
    float vr = (float)(m * cos(a));
    float vi = (float)(m * sin(a));

    const size_t kcbase = (size_t)(p >> 6) * 16384;
    const int kk = p & 63;

    #pragma unroll 4
    for (int t = 0; t < 128; t++) {
        int l = l0 + t;
        float vs = vr + vi;
        __nv_bfloat16 hr = __float2bfloat16_rn(vr);
        __nv_bfloat16 hi = __float2bfloat16_rn(vi);
        __nv_bfloat16 hs = __float2bfloat16_rn(vs);
        size_t o = (kcbase + l) * 64 + kk;
        g_B[0][o] = hr; g_B[1][o] = __float2bfloat16_rn(vr - __bfloat162float(hr));
        g_B[2][o] = hi; g_B[3][o] = __float2bfloat16_rn(vi - __bfloat162float(hi));
        g_B[4][o] = hs; g_B[5][o] = __float2bfloat16_rn(vs - __bfloat162float(hs));
        float nvr = vr * ab.x - vi * ab.y;
        float nvi = vr * ab.y + vi * ab.x;
        vr = nvr; vi = nvi;
    }
}

// ---------------------------------------------------------------------------
// k_gemm: z-batched 3 real GEMMs, CTA tile 128m x 256n, 512 thr (16 warps
// 4x4, warp tile 32m x 64n), 2-stage cp.async pipeline (192 KB smem).
// Per ks-step: B-hi frags shared by A-hi and A-lo products (8 LDSM / 48 MMA).
// Stage layout: [Ahi 16K][Alo 16K][Bhi 32K][Blo 32K].
// ---------------------------------------------------------------------------
__global__ __launch_bounds__(512, 1) void k_gemm() {
    extern __shared__ char smp[];
    const int tid  = threadIdx.x;
    const int lane = tid & 31;
    const int wid  = tid >> 5;
    const int wm   = wid >> 2;            // 0..3 (m 32 each)
    const int wn   = wid & 3;             // 0..3 (n 64 each)
    const int m0   = blockIdx.x * 128;
    const int n0   = blockIdx.y * 256;
    const int z    = blockIdx.z;          // 0=r, 1=i, 2=s
    const uint32_t sb = s2u(smp);

    const __nv_bfloat16* Agh = g_A[2 * z];
    const __nv_bfloat16* Agl = g_A[2 * z + 1];
    const __nv_bfloat16* Bgh = g_B[2 * z];
    const __nv_bfloat16* Bgl = g_B[2 * z + 1];

    float acc[2][8][4];
    #pragma unroll
    for (int i = 0; i < 2; i++)
        #pragma unroll
        for (int j = 0; j < 8; j++)
            #pragma unroll
            for (int t = 0; t < 4; t++) acc[i][j][t] = 0.0f;

    // cp.async staging: A planes 128x8 slots (2/thread/plane),
    //                   B planes 256x8 slots (4/thread/plane)
    const int arow = tid >> 2, acol = tid & 3;
    const int brow = tid >> 1, bcol = tid & 1;

    auto issue = [&](int kc, int s) {
        uint32_t st = sb + s * STAGE_BYTES;
        #pragma unroll
        for (int j = 0; j < 2; j++) {
            int col = acol + 4 * j;
            uint32_t d = st + arow * 128 + ((col ^ (arow & 7)) << 4);
            size_t oA = ((size_t)kc * 256 + m0 + arow) * 64 + col * 8;
            cpa(d,         Agh + oA);
            cpa(d + 16384, Agl + oA);
        }
        #pragma unroll
        for (int j = 0; j < 4; j++) {
            int col = bcol + 2 * j;
            uint32_t d = st + 32768 + brow * 128 + ((col ^ (brow & 7)) << 4);
            size_t oB = ((size_t)kc * 16384 + n0 + brow) * 64 + col * 8;
            cpa(d,         Bgh + oB);
            cpa(d + 32768, Bgl + oB);
        }
        asm volatile("cp.async.commit_group;" ::: "memory");
    };

    const int r15 = lane & 15, h16 = lane >> 4;
    const int rA = wm * 32 + r15;          // A rows rA, rA+16
    const int rB = wn * 64 + r15;          // B rows rB, +16, +32, +48

    issue(0, 0);

    for (int k = 0; k < NKC; k++) {
        const int s = k & 1;
        if (k + 1 < NKC) {
            issue(k + 1, s ^ 1);
            asm volatile("cp.async.wait_group 1;" ::: "memory");
        } else {
            asm volatile("cp.async.wait_group 0;" ::: "memory");
        }
        __syncthreads();

        const uint32_t sA = sb + s * STAGE_BYTES;          // A hi
        const uint32_t sB = sA + 32768;                     // B hi (lo at +32768)

        #pragma unroll
        for (int ks = 0; ks < 4; ks++) {
            const int cc = 2 * ks + h16;
            const uint32_t oA = rA * 128 + ((cc ^ (rA & 7)) << 4);
            const uint32_t oB = rB * 128 + ((cc ^ (rB & 7)) << 4);

            uint32_t a0[4], a1[4], al0[4], al1[4], bb[16];
            ldm4(a0,  sA + oA);
            ldm4(a1,  sA + oA + 2048);
            ldm4(al0, sA + 16384 + oA);
            ldm4(al1, sA + 16384 + oA + 2048);
            #pragma unroll
            for (int j = 0; j < 4; j++)
                ldm4(&bb[4 * j], sB + oB + 2048 * j);

            // hi*hi and lo*hi with shared B-hi fragments
            #pragma unroll
            for (int j = 0; j < 4; j++) {
                mma16816(acc[0][2 * j],     a0,  bb[4 * j],     bb[4 * j + 2]);
                mma16816(acc[0][2 * j + 1], a0,  bb[4 * j + 1], bb[4 * j + 3]);
                mma16816(acc[1][2 * j],     a1,  bb[4 * j],     bb[4 * j + 2]);
                mma16816(acc[1][2 * j + 1], a1,  bb[4 * j + 1], bb[4 * j + 3]);
            }
            #pragma unroll
            for (int j = 0; j < 4; j++) {
                mma16816(acc[0][2 * j],     al0, bb[4 * j],     bb[4 * j + 2]);
                mma16816(acc[0][2 * j + 1], al0, bb[4 * j + 1], bb[4 * j + 3]);
                mma16816(acc[1][2 * j],     al1, bb[4 * j],     bb[4 * j + 2]);
                mma16816(acc[1][2 * j + 1], al1, bb[4 * j + 1], bb[4 * j + 3]);
            }
            // overwrite bb with B-lo, hi*lo products
            #pragma unroll
            for (int j = 0; j < 4; j++)
                ldm4(&bb[4 * j], sB + 32768 + oB + 2048 * j);
            #pragma unroll
            for (int j = 0; j < 4; j++) {
                mma16816(acc[0][2 * j],     a0,  bb[4 * j],     bb[4 * j + 2]);
                mma16816(acc[0][2 * j + 1], a0,  bb[4 * j + 1], bb[4 * j + 3]);
                mma16816(acc[1][2 * j],     a1,  bb[4 * j],     bb[4 * j + 2]);
                mma16816(acc[1][2 * j + 1], a1,  bb[4 * j + 1], bb[4 * j + 3]);
            }
        }
        __syncthreads();
    }

    // Epilogue -> fp32 partial plane
    float* G = g_G[z];
    const int mrow = lane >> 2, ncol = (lane & 3) * 2;
    #pragma unroll
    for (int im = 0; im < 2; im++) {
        int m = m0 + wm * 32 + im * 16 + mrow;
        #pragma unroll
        for (int jn = 0; jn < 8; jn++) {
            int n = n0 + wn * 64 + jn * 8 + ncol;
            float* p = G + (size_t)m * Ldim + n;
            *(float2*)p = make_float2(acc[im][jn][0], acc[im][jn][1]);
            *(float2*)(p + (size_t)8 * Ldim) = make_float2(acc[im][jn][2], acc[im][jn][3]);
        }
    }
}

// ---------------------------------------------------------------------------
// k_comb: out[h][l] = (Gr-Gi, Gm-Gr-Gi), vectorized float4.
// ---------------------------------------------------------------------------
__global__ void k_comb(float4* __restrict__ out) {
    size_t idx = (size_t)blockIdx.x * 256 + threadIdx.x;   // over H*L/4
    const float4* Gr = (const float4*)g_G[0];
    const float4* Gi = (const float4*)g_G[1];
    const float4* Gm = (const float4*)g_G[2];
    float4 r = Gr[idx], i = Gi[idx], m = Gm[idx];
    out[2 * idx] = make_float4(r.x - i.x, m.x - r.x - i.x,
                               r.y - i.y, m.y - r.y - i.y);
    out[2 * idx + 1] = make_float4(r.z - i.z, m.z - r.z - i.z,
                                   r.w - i.w, m.w - r.w - i.w);
}

// ---------------------------------------------------------------------------
extern "C" void kernel_launch(void* const* d_in, const int* in_sizes, int n_in,
                              void* d_out, int out_size) {
    const float* A = (const float*)d_in[0];
    const float* B = (const float*)d_in[1];
    const float* C = (const float*)d_in[2];

    cudaFuncSetAttribute(k_gemm, cudaFuncAttributeMaxDynamicSharedMemorySize, 196608);

    k_pre<<<4, 256>>>(A);
    k_setupA<<<1024, 256>>>(B, C);
    k_genB<<<512, 256>>>();
    k_gemm<<<dim3(2, 64, 3), 512, 196608>>>();
    k_comb<<<4096, 256>>>((float4*)d_out);
}